// round 15
// baseline (speedup 1.0000x reference)
#include <cuda_runtime.h>
#include <cuda_bf16.h>
#include <math.h>

#define Dv 256
#define Tt 256
#define Bn 16
#define Mm 32
#define Vv 50257
#define PITCH 260
#define EPSv 1e-6f

// ------------------------ device scratch (no allocs allowed) ------------------
__device__ float gA1[Dv*Dv], gA2[Dv*Dv];       // Wq^T @ Wk
__device__ float gKmv1[Mm*Dv], gKmv2[Mm*Dv];   // mover @ Wk^T + bk
__device__ float gVmv1[Mm*Dv], gVmv2[Mm*Dv];   // mover @ Wv^T + bv
__device__ float gU1[Mm*Dv], gU2[Mm*Dv];       // Wq^T Kmv[m]
__device__ float gu1[Dv], gu2[Dv];             // bq^T Wk + bk^T Wq
__device__ float gc1[Mm], gc2[Mm];             // bq . Kmv[m]
__device__ float gc0v[2];                      // bq . bk
__device__ float gZfin[Bn*Dv];
__device__ float gLse[Bn];

// ------------------------ helpers ------------------------
__device__ __forceinline__ unsigned smem_u32(const void* p){
  unsigned a;
  asm("{ .reg .u64 t; cvta.to.shared.u64 t, %1; cvt.u32.u64 %0, t; }" : "=r"(a) : "l"(p));
  return a;
}
__device__ __forceinline__ unsigned mapa_rank(unsigned a, int r){
  unsigned d2; asm("mapa.shared::cluster.u32 %0, %1, %2;" : "=r"(d2) : "r"(a), "r"(r));
  return d2;
}
__device__ __forceinline__ void st_cluster_f32(unsigned a, float v){
  asm volatile("st.shared::cluster.f32 [%0], %1;" :: "r"(a), "f"(v) : "memory");
}
__device__ __forceinline__ void cluster_sync(){
  asm volatile("barrier.cluster.arrive.aligned;" ::: "memory");
  asm volatile("barrier.cluster.wait.aligned;"   ::: "memory");
}
__device__ __forceinline__ float wsum(float v){
  #pragma unroll
  for (int o = 16; o; o >>= 1) v += __shfl_xor_sync(0xffffffffu, v, o);
  return v;
}
__device__ __forceinline__ float wmax(float v){
  #pragma unroll
  for (int o = 16; o; o >>= 1) v = fmaxf(v, __shfl_xor_sync(0xffffffffu, v, o));
  return v;
}

// ------------------------ precompute kernels ------------------------
// A[d][e] = sum_j Wq[j][d]*Wk[j][e]
__global__ void pk_A(const float* Wq1, const float* Wk1,
                     const float* Wq2, const float* Wk2){
  int d = blockIdx.x, which = blockIdx.y;
  const float* Wq = which ? Wq2 : Wq1;
  const float* Wk = which ? Wk2 : Wk1;
  float* A = which ? gA2 : gA1;
  __shared__ float col[Dv];
  col[threadIdx.x] = Wq[threadIdx.x*Dv + d];
  __syncthreads();
  int e = threadIdx.x;
  float acc = 0.f;
  #pragma unroll 8
  for (int j = 0; j < Dv; j++) acc += col[j]*Wk[j*Dv + e];
  A[d*Dv + e] = acc;
}

// Kmv/Vmv: out[m][j] = sum_d mv[m][d]*W[j][d] + b[j]
__global__ void pk_KV(const float* mv1, const float* mv2,
                      const float* Wk1, const float* bk1,
                      const float* Wk2, const float* bk2,
                      const float* Wv1, const float* bv1,
                      const float* Wv2, const float* bv2){
  int m = blockIdx.x, which = blockIdx.y;
  const float* mv = (which & 1) ? mv2 : mv1;
  const float* W  = (which==0) ? Wk1 : (which==1) ? Wk2 : (which==2) ? Wv1 : Wv2;
  const float* bb = (which==0) ? bk1 : (which==1) ? bk2 : (which==2) ? bv1 : bv2;
  float* out      = (which==0) ? gKmv1 : (which==1) ? gKmv2 : (which==2) ? gVmv1 : gVmv2;
  __shared__ float ms[Dv];
  ms[threadIdx.x] = mv[m*Dv + threadIdx.x];
  __syncthreads();
  int j = threadIdx.x;
  float acc = bb[j];
  #pragma unroll 8
  for (int d = 0; d < Dv; d++) acc += ms[d]*W[j*Dv + d];
  out[m*Dv + j] = acc;
}

// u[d] = sum_j bq[j]*Wk[j][d] + bk[j]*Wq[j][d];  c0 = bq.bk
__global__ void pk_u(const float* bq1, const float* Wk1, const float* bk1, const float* Wq1,
                     const float* bq2, const float* Wk2, const float* bk2, const float* Wq2){
  int which = blockIdx.x;
  const float* bq = which ? bq2 : bq1; const float* Wk = which ? Wk2 : Wk1;
  const float* bk = which ? bk2 : bk1; const float* Wq = which ? Wq2 : Wq1;
  float* u = which ? gu2 : gu1;
  int d = threadIdx.x;
  float acc = 0.f;
  #pragma unroll 8
  for (int j = 0; j < Dv; j++) acc += bq[j]*Wk[j*Dv + d] + bk[j]*Wq[j*Dv + d];
  u[d] = acc;
  if (d == 0){
    float c = 0.f;
    for (int j = 0; j < Dv; j++) c += bq[j]*bk[j];
    gc0v[which] = c;
  }
}

// U[m][d] = sum_j Kmv[m][j]*Wq[j][d];  c[m] = bq.Kmv[m]   (after pk_KV)
__global__ void pk_U(const float* Wq1, const float* bq1,
                     const float* Wq2, const float* bq2){
  int m = blockIdx.x, which = blockIdx.y;
  const float* Km = which ? gKmv2 : gKmv1;
  const float* Wq = which ? Wq2 : Wq1;
  const float* bq = which ? bq2 : bq1;
  float* U = which ? gU2 : gU1;
  float* c = which ? gc2 : gc1;
  __shared__ float km[Dv];
  km[threadIdx.x] = Km[m*Dv + threadIdx.x];
  __syncthreads();
  int d = threadIdx.x;
  float acc = 0.f;
  #pragma unroll 8
  for (int j = 0; j < Dv; j++) acc += km[j]*Wq[j*Dv + d];
  U[m*Dv + d] = acc;
  if (d == 0){
    float cc = 0.f;
    for (int j = 0; j < Dv; j++) cc += bq[j]*km[j];
    c[m] = cc;
  }
}

// ------------------------ smem layout for recurrent kernel (floats) ----------
#define OFF_AS    0                       // [4][32][PITCH]
#define OFF_U1C   (OFF_AS + 4*32*PITCH)   // [4][256]
#define OFF_U2C   (OFF_U1C + 4*Dv)        // [4][256]
#define OFF_VM1   (OFF_U2C + 4*Dv)        // [32][32]
#define OFF_VM2   (OFF_VM1 + Mm*32)       // [32][32]
#define OFF_C1    (OFF_VM2 + Mm*32)       // [32]
#define OFF_C2    (OFF_C1 + Mm)           // [32]
#define OFF_UIN   (OFF_C2 + Mm)           // [4][32]
#define OFF_ZC    (OFF_UIN + 4*32)        // [256]
#define OFF_HV    (OFF_ZC + Dv)           // [256]
#define OFF_YB    (OFF_HV + Dv)           // [256]
#define OFF_PR    (OFF_YB + Dv)           // [8][32]
#define OFF_RES   (OFF_PR + 8*32)         // [4][32]
#define OFF_AW1   (OFF_RES + 4*32)        // [34]
#define OFF_AW2   (OFF_AW1 + 34)          // [34]
#define OFF_SCB   (OFF_AW2 + 34)          // [8][12]
#define OFF_LNP   (OFF_SCB + 8*12)        // [8][2]
#define OFF_YL    (OFF_LNP + 16)          // [32]
#define OFF_GAM   (OFF_YL + 32)           // [256]
#define OFF_BET   (OFF_GAM + Dv)          // [256]
#define OFF_C0    (OFF_BET + Dv)          // [2]
#define OFF_TOK   (OFF_C0 + 2)            // [1] int
#define SMEM_FLOATS (OFF_TOK + 4)
#define SMEM_BYTES (SMEM_FLOATS*4)

// ------------------------ recurrent kernel ------------------------
// grid (8,16), block 256, cluster (8,1,1): one cluster per batch.
__global__ void __cluster_dims__(8,1,1) __launch_bounds__(256,1)
rnn_kernel(const float* __restrict__ hidden, const int* __restrict__ seq,
           const float* __restrict__ emb,
           const float* __restrict__ Wv1, const float* __restrict__ bv1,
           const float* __restrict__ Wv2, const float* __restrict__ bv2,
           const float* __restrict__ gamma, const float* __restrict__ beta,
           float* __restrict__ out)
{
  extern __shared__ float sm[];
  const int rank = blockIdx.x;      // cluster ctarank (cluster spans x)
  const int b    = blockIdx.y;
  const int tid  = threadIdx.x;
  const int w    = tid >> 5, l = tid & 31;
  const int base = rank * 32;

  float* As  = sm + OFF_AS;
  float* U1c = sm + OFF_U1C; float* U2c = sm + OFF_U2C;
  float* Vm1 = sm + OFF_VM1; float* Vm2 = sm + OFF_VM2;
  float* c1s = sm + OFF_C1;  float* c2s = sm + OFF_C2;
  float* uin = sm + OFF_UIN;
  float* zc  = sm + OFF_ZC;  float* hv  = sm + OFF_HV;
  float* yb  = sm + OFF_YB;
  float* pr  = sm + OFF_PR;  float* res = sm + OFF_RES;
  float* aw1 = sm + OFF_AW1; float* aw2 = sm + OFF_AW2;
  float* scb = sm + OFF_SCB; float* lnp = sm + OFF_LNP;
  float* yl  = sm + OFF_YL;
  float* gam = sm + OFF_GAM; float* bet = sm + OFF_BET;
  float* c0s = sm + OFF_C0;
  int*  stok = (int*)(sm + OFF_TOK);

  // ---- init loads ----
  // matrix chunks: mat0=A1, mat1=Wv1, mat2=A2, mat3=Wv2 ; rows [base, base+32)
  {
    const float* srcs[4] = { gA1, Wv1, gA2, Wv2 };
    #pragma unroll
    for (int mat = 0; mat < 4; mat++){
      const float* s = srcs[mat];
      for (int idx = tid; idx < 32*Dv; idx += 256){
        int r = idx >> 8, c = idx & 255;
        As[(mat*32 + r)*PITCH + c] = s[(base + r)*Dv + c];
      }
    }
  }
  for (int idx = tid; idx < 4*Dv; idx += 256){
    U1c[idx] = gU1[(4*rank)*Dv + idx];
    U2c[idx] = gU2[(4*rank)*Dv + idx];
  }
  for (int idx = tid; idx < Mm*32; idx += 256){
    int m = idx >> 5, j = idx & 31;
    Vm1[idx] = gVmv1[m*Dv + base + j];
    Vm2[idx] = gVmv2[m*Dv + base + j];
  }
  if (tid < Mm){ c1s[tid] = gc1[tid]; c2s[tid] = gc2[tid]; }
  if (tid < 32){
    uin[0*32 + tid] = gu1[base + tid];
    uin[1*32 + tid] = bv1[base + tid];
    uin[2*32 + tid] = gu2[base + tid];
    uin[3*32 + tid] = bv2[base + tid];
  }
  gam[tid] = gamma[tid]; bet[tid] = beta[tid];
  if (tid < 2) c0s[tid] = gc0v[tid];
  {
    int tok0 = seq[b*Tt];
    zc[tid] = hidden[b*2*Dv + tid] + emb[tok0*Dv + tid] * 16.0f;
    hv[tid] = hidden[b*2*Dv + Dv + tid];
  }
  __syncthreads();
  cluster_sync();  // peers' boards exist before anyone writes DSMEM

  const unsigned scb_a = smem_u32(scb);
  const unsigned lnp_a = smem_u32(lnp);
  const unsigned yb_a  = smem_u32(yb);

  float hn = 0.f;

  for (int t = 0; t < Tt; t++){
    // prefetch next token index (consume at STS below, hidden behind matvec)
    int tknext = 0;
    if (tid == 0 && t + 1 < Tt) tknext = __ldg(seq + b*Tt + t + 1);

    // ---- phase A: matvecs (warp w: matrix w/2, half w&1, row l, 128 cols) ----
    {
      int mat = w >> 1, half = w & 1;
      const float* Arow = As + (mat*32 + l)*PITCH + half*128;
      const float* zin  = (mat < 2) ? zc : hv;
      const float4* a4  = (const float4*)Arow;
      const float4* z4  = (const float4*)(zin + half*128);
      float acc = half ? 0.f : uin[mat*32 + l];
      #pragma unroll
      for (int i = 0; i < 32; i++){
        float4 a = a4[i]; float4 z = z4[i];
        acc += a.x*z.x; acc += a.y*z.y; acc += a.z*z.z; acc += a.w*z.w;
      }
      pr[w*32 + l] = acc;
    }
    // mover score dots: warp w -> head w/4, local mover w&3
    {
      int head = w >> 2, ml = w & 3;
      const float* Uv = (head ? U2c : U1c) + ml*Dv;
      const float* zz = head ? hv : zc;
      float md = 0.f;
      #pragma unroll
      for (int i = 0; i < 8; i++) md += Uv[l + 32*i] * zz[l + 32*i];
      md = wsum(md);
      md += (head ? c2s : c1s)[rank*4 + ml];
      if (l < 8) st_cluster_f32(mapa_rank(scb_a + (rank*12 + w)*4, l), md);
    }
    if (tid == 0 && t + 1 < Tt) *stok = tknext;
    __syncthreads();

    // prefetch next x into register (hidden behind syncs below)
    float xn = 0.f;
    if (t + 1 < Tt) xn = __ldg(emb + (size_t)(*stok)*Dv + tid) * 16.0f;

    // combine halves; self-score partials
    if (tid < 128){
      int m2 = tid >> 5, j = tid & 31;
      float r = pr[(2*m2)*32 + j] + pr[(2*m2 + 1)*32 + j];
      res[m2*32 + j] = r;
      if (m2 == 0){
        float pp = wsum(zc[base + j] * r);
        if (j < 8) st_cluster_f32(mapa_rank(scb_a + (rank*12 + 8)*4, j), pp);
      }
      if (m2 == 2){
        float pp = wsum(hv[base + j] * r);
        if (j < 8) st_cluster_f32(mapa_rank(scb_a + (rank*12 + 9)*4, j), pp);
      }
    }
    cluster_sync();   // phase A barrier

    // ---- softmax (warp0: head1, warp1: head2), redundant per CTA ----
    if (w < 2){
      int head = w;
      float s = scb[(l >> 2)*12 + head*4 + (l & 3)] * 0.0625f;
      float ps = c0s[head];
      #pragma unroll
      for (int r2 = 0; r2 < 8; r2++) ps += scb[r2*12 + 8 + head];
      ps *= 0.0625f;
      float mx = fmaxf(wmax(s), ps);
      float e  = expf(s - mx);
      float es = wsum(e);
      float eself = expf(ps - mx);
      float inv = 1.0f / (es + eself);
      float* awp = head ? aw2 : aw1;
      awp[l] = e * inv;
      if (l == 0) awp[32] = eself * inv;
    }
    __syncthreads();

    // ---- y chunk + LN partials (warp0) ----
    if (w == 0){
      float dg = aw1[32]*res[1*32 + l] + aw2[32]*res[3*32 + l];
      #pragma unroll 8
      for (int m = 0; m < Mm; m++)
        dg += aw1[m]*Vm1[m*32 + l] + aw2[m]*Vm2[m*32 + l];
      float y = zc[base + l] + dg;
      yl[l] = y;
      float s1 = wsum(y);
      float s2 = wsum(y*y);
      if (l < 8)       st_cluster_f32(mapa_rank(lnp_a + (rank*2 + 0)*4, l), s1);
      else if (l < 16) st_cluster_f32(mapa_rank(lnp_a + (rank*2 + 1)*4, l - 8), s2);
    }
    __syncthreads();
    {
      int peer = tid >> 5, j = tid & 31;
      st_cluster_f32(mapa_rank(yb_a + (base + j)*4, peer), yl[j]);
    }
    cluster_sync();   // phase B barrier

    // ---- layernorm, replicated ----
    {
      float s1t = 0.f, s2t = 0.f;
      #pragma unroll
      for (int r2 = 0; r2 < 8; r2++){ s1t += lnp[r2*2]; s2t += lnp[r2*2 + 1]; }
      float mu  = s1t * (1.0f/Dv);
      float var = s2t * (1.0f/Dv) - mu*mu;
      float rs  = rsqrtf(var + EPSv);
      hn = (yb[tid] - mu)*rs*gam[tid] + bet[tid];
      hv[tid] = hn;
      zc[tid] = hn + xn;
    }
    __syncthreads();
  }

  // ---- final state: both output rows equal z_final ----
  if (rank == 0){
    out[b*2*Dv + tid]      = hn;
    out[b*2*Dv + Dv + tid] = hn;
    gZfin[b*Dv + tid]      = hn;
  }
}

// ------------------------ vocab epilogue ------------------------
// logits[b][v] = zfin[b].Wvoc[v] + bvoc[v]; write into y region of d_out.
__global__ void __launch_bounds__(256) k_logits(const float* __restrict__ Wvoc,
                                                const float* __restrict__ bvoc,
                                                float* __restrict__ yout)
{
  __shared__ float zT[Dv*16];      // [d][b]
  __shared__ float Ws[16*260];
  int tid = threadIdx.x;
  for (int i = 0; i < 16; i++){
    int idx = tid + i*256;
    int bb = idx >> 8, d = idx & 255;
    zT[d*16 + bb] = gZfin[bb*Dv + d];
  }
  int v0 = blockIdx.x * 64;
  __syncthreads();
  for (int pass = 0; pass < 4; pass++){
    int vb = v0 + pass*16;
    for (int i = 0; i < 16; i++){
      int idx = tid + i*256;
      int r = idx >> 8, c = idx & 255;
      Ws[r*260 + c] = (vb + r < Vv) ? Wvoc[(size_t)(vb + r)*Dv + c] : 0.f;
    }
    __syncthreads();
    int bb = tid >> 4, vl = tid & 15;
    int v = vb + vl;
    float acc = (v < Vv) ? bvoc[v] : 0.f;
    #pragma unroll 8
    for (int d = 0; d < Dv; d++) acc += Ws[vl*260 + d]*zT[d*16 + bb];
    if (v < Vv) yout[(size_t)bb*Vv + v] = acc;
    __syncthreads();
  }
}

__global__ void k_lse(const float* __restrict__ yout){
  int b = blockIdx.x, tid = threadIdx.x;
  __shared__ float red[256];
  float mx = -1e30f;
  for (int v = tid; v < Vv; v += 256) mx = fmaxf(mx, yout[(size_t)b*Vv + v]);
  red[tid] = mx; __syncthreads();
  for (int s = 128; s; s >>= 1){ if (tid < s) red[tid] = fmaxf(red[tid], red[tid + s]); __syncthreads(); }
  mx = red[0]; __syncthreads();
  float sum = 0.f;
  for (int v = tid; v < Vv; v += 256) sum += expf(yout[(size_t)b*Vv + v] - mx);
  red[tid] = sum; __syncthreads();
  for (int s = 128; s; s >>= 1){ if (tid < s) red[tid] += red[tid + s]; __syncthreads(); }
  if (tid == 0) gLse[b] = mx + logf(red[0]);
}

__global__ void k_sub(float* __restrict__ yout){
  int i = blockIdx.x*256 + threadIdx.x;
  if (i < Bn*Vv) yout[i] -= gLse[i / Vv];
}

// ------------------------ launch ------------------------
extern "C" void kernel_launch(void* const* d_in, const int* in_sizes, int n_in,
                              void* d_out, int out_size)
{
  const float* hidden = (const float*)d_in[0];
  const int*   seq    = (const int*)  d_in[1];
  const float* emb    = (const float*)d_in[2];
  const float* Wq1 = (const float*)d_in[3];  const float* bq1 = (const float*)d_in[4];
  const float* Wk1 = (const float*)d_in[5];  const float* bk1 = (const float*)d_in[6];
  const float* Wv1 = (const float*)d_in[7];  const float* bv1 = (const float*)d_in[8];
  const float* Wq2 = (const float*)d_in[9];  const float* bq2 = (const float*)d_in[10];
  const float* Wk2 = (const float*)d_in[11]; const float* bk2 = (const float*)d_in[12];
  const float* Wv2 = (const float*)d_in[13]; const float* bv2 = (const float*)d_in[14];
  const float* mv1 = (const float*)d_in[15]; const float* mv2 = (const float*)d_in[16];
  const float* gamma = (const float*)d_in[17];
  const float* beta  = (const float*)d_in[18];
  const float* Wvoc  = (const float*)d_in[19];
  const float* bvoc  = (const float*)d_in[20];
  float* out = (float*)d_out;
  float* yout = out + Bn*2*Dv;

  cudaFuncSetAttribute(rnn_kernel, cudaFuncAttributeMaxDynamicSharedMemorySize, SMEM_BYTES);

  pk_A <<<dim3(Dv, 2), 256>>>(Wq1, Wk1, Wq2, Wk2);
  pk_KV<<<dim3(Mm, 4), 256>>>(mv1, mv2, Wk1, bk1, Wk2, bk2, Wv1, bv1, Wv2, bv2);
  pk_u <<<2, 256>>>(bq1, Wk1, bk1, Wq1, bq2, Wk2, bk2, Wq2);
  pk_U <<<dim3(Mm, 2), 256>>>(Wq1, bq1, Wq2, bq2);

  rnn_kernel<<<dim3(8, Bn), 256, SMEM_BYTES>>>(hidden, seq, emb, Wv1, bv1, Wv2, bv2,
                                               gamma, beta, out);

  k_logits<<<(Vv + 63)/64, 256>>>(Wvoc, bvoc, yout);
  k_lse<<<Bn, 256>>>(yout);
  k_sub<<<(Bn*Vv + 255)/256, 256>>>(yout);
}

// round 17
// speedup vs baseline: 1.2432x; 1.2432x over previous
#include <cuda_runtime.h>
#include <cuda_bf16.h>
#include <math.h>

#define Dv 256
#define Tt 256
#define Bn 16
#define Mm 32
#define Vv 50257
#define EPSv 1e-6f

typedef unsigned long long ull;

// ------------------------ device scratch (no allocs allowed) ------------------
__device__ float gA1[Dv*Dv], gA2[Dv*Dv];       // Wq^T @ Wk
__device__ float gKmv1[Mm*Dv], gKmv2[Mm*Dv];   // mover @ Wk^T + bk
__device__ float gVmv1[Mm*Dv], gVmv2[Mm*Dv];   // mover @ Wv^T + bv
__device__ float gU1[Mm*Dv], gU2[Mm*Dv];       // Wq^T Kmv[m]
__device__ float gu1[Dv], gu2[Dv];             // bq^T Wk + bk^T Wq
__device__ float gc1[Mm], gc2[Mm];             // bq . Kmv[m]
__device__ float gc0v[2];                      // bq . bk
__device__ float gZfin[Bn*Dv];
__device__ float gLse[Bn];

// ------------------------ helpers ------------------------
__device__ __forceinline__ unsigned smem_u32(const void* p){
  unsigned a;
  asm("{ .reg .u64 t; cvta.to.shared.u64 t, %1; cvt.u32.u64 %0, t; }" : "=r"(a) : "l"(p));
  return a;
}
__device__ __forceinline__ unsigned mapa_rank(unsigned a, int r){
  unsigned d2; asm("mapa.shared::cluster.u32 %0, %1, %2;" : "=r"(d2) : "r"(a), "r"(r));
  return d2;
}
__device__ __forceinline__ void st_cluster_f32(unsigned a, float v){
  asm volatile("st.shared::cluster.f32 [%0], %1;" :: "r"(a), "f"(v) : "memory");
}
__device__ __forceinline__ void cluster_sync(){
  asm volatile("barrier.cluster.arrive.aligned;" ::: "memory");
  asm volatile("barrier.cluster.wait.aligned;"   ::: "memory");
}
__device__ __forceinline__ float wsum(float v){
  #pragma unroll
  for (int o = 16; o; o >>= 1) v += __shfl_xor_sync(0xffffffffu, v, o);
  return v;
}
__device__ __forceinline__ float wmax(float v){
  #pragma unroll
  for (int o = 16; o; o >>= 1) v = fmaxf(v, __shfl_xor_sync(0xffffffffu, v, o));
  return v;
}
__device__ __forceinline__ ull fma2(ull a, ull b, ull c){
  ull d; asm("fma.rn.f32x2 %0, %1, %2, %3;" : "=l"(d) : "l"(a), "l"(b), "l"(c));
  return d;
}
__device__ __forceinline__ ull add2(ull a, ull b){
  ull d; asm("add.rn.f32x2 %0, %1, %2;" : "=l"(d) : "l"(a), "l"(b));
  return d;
}
__device__ __forceinline__ float lo32(ull x){ return __uint_as_float((unsigned)x); }
__device__ __forceinline__ float hi32(ull x){ return __uint_as_float((unsigned)(x >> 32)); }

// ------------------------ precompute kernels (unchanged, passing) -------------
__global__ void pk_A(const float* Wq1, const float* Wk1,
                     const float* Wq2, const float* Wk2){
  int d = blockIdx.x, which = blockIdx.y;
  const float* Wq = which ? Wq2 : Wq1;
  const float* Wk = which ? Wk2 : Wk1;
  float* A = which ? gA2 : gA1;
  __shared__ float col[Dv];
  col[threadIdx.x] = Wq[threadIdx.x*Dv + d];
  __syncthreads();
  int e = threadIdx.x;
  float acc = 0.f;
  #pragma unroll 8
  for (int j = 0; j < Dv; j++) acc += col[j]*Wk[j*Dv + e];
  A[d*Dv + e] = acc;
}

__global__ void pk_KV(const float* mv1, const float* mv2,
                      const float* Wk1, const float* bk1,
                      const float* Wk2, const float* bk2,
                      const float* Wv1, const float* bv1,
                      const float* Wv2, const float* bv2){
  int m = blockIdx.x, which = blockIdx.y;
  const float* mv = (which & 1) ? mv2 : mv1;
  const float* W  = (which==0) ? Wk1 : (which==1) ? Wk2 : (which==2) ? Wv1 : Wv2;
  const float* bb = (which==0) ? bk1 : (which==1) ? bk2 : (which==2) ? bv1 : bv2;
  float* out      = (which==0) ? gKmv1 : (which==1) ? gKmv2 : (which==2) ? gVmv1 : gVmv2;
  __shared__ float ms[Dv];
  ms[threadIdx.x] = mv[m*Dv + threadIdx.x];
  __syncthreads();
  int j = threadIdx.x;
  float acc = bb[j];
  #pragma unroll 8
  for (int d = 0; d < Dv; d++) acc += ms[d]*W[j*Dv + d];
  out[m*Dv + j] = acc;
}

__global__ void pk_u(const float* bq1, const float* Wk1, const float* bk1, const float* Wq1,
                     const float* bq2, const float* Wk2, const float* bk2, const float* Wq2){
  int which = blockIdx.x;
  const float* bq = which ? bq2 : bq1; const float* Wk = which ? Wk2 : Wk1;
  const float* bk = which ? bk2 : bk1; const float* Wq = which ? Wq2 : Wq1;
  float* u = which ? gu2 : gu1;
  int d = threadIdx.x;
  float acc = 0.f;
  #pragma unroll 8
  for (int j = 0; j < Dv; j++) acc += bq[j]*Wk[j*Dv + d] + bk[j]*Wq[j*Dv + d];
  u[d] = acc;
  if (d == 0){
    float c = 0.f;
    for (int j = 0; j < Dv; j++) c += bq[j]*bk[j];
    gc0v[which] = c;
  }
}

__global__ void pk_U(const float* Wq1, const float* bq1,
                     const float* Wq2, const float* bq2){
  int m = blockIdx.x, which = blockIdx.y;
  const float* Km = which ? gKmv2 : gKmv1;
  const float* Wq = which ? Wq2 : Wq1;
  const float* bq = which ? bq2 : bq1;
  float* U = which ? gU2 : gU1;
  float* c = which ? gc2 : gc1;
  __shared__ float km[Dv];
  km[threadIdx.x] = Km[m*Dv + threadIdx.x];
  __syncthreads();
  int d = threadIdx.x;
  float acc = 0.f;
  #pragma unroll 8
  for (int j = 0; j < Dv; j++) acc += km[j]*Wq[j*Dv + d];
  U[m*Dv + d] = acc;
  if (d == 0){
    float cc = 0.f;
    for (int j = 0; j < Dv; j++) cc += bq[j]*km[j];
    c[m] = cc;
  }
}

// ------------------------ recurrent kernel ------------------------
// grid (8,16), block 256, cluster (8,1,1): one cluster per batch.
// Register-resident per thread: 32-row chunk columns of one matrix half (aR, 64 ull),
// mover V pair column (VmP, 32 ull), mover-U slice (uR, 8), gamma/beta/bias.
// ONE cluster sync per step; scoreboards double-buffered.
__global__ void __cluster_dims__(8,1,1) __launch_bounds__(256,1)
rnn_kernel(const float* __restrict__ hidden, const int* __restrict__ seq,
           const float* __restrict__ emb,
           const float* __restrict__ Wv1, const float* __restrict__ bv1,
           const float* __restrict__ Wv2, const float* __restrict__ bv2,
           const float* __restrict__ gamma, const float* __restrict__ beta,
           float* __restrict__ out)
{
  __shared__ __align__(16) float zc[Dv];
  __shared__ __align__(16) float hv[Dv];
  __shared__ __align__(16) float pr[8*32];
  __shared__ __align__(16) float awI[64];       // interleaved (aw1[m], aw2[m])
  __shared__ float awS[2];                      // self weights per head
  __shared__ float sc[2][64];                   // [buf][head*32+m] mover scores
  __shared__ float selfp[2][16];                // [buf][rank*2+head] self partials
  __shared__ __align__(16) float vb[2][2][Dv];  // [buf][head][j] self-value vectors
  __shared__ float lnp[16];                     // [warp*2 + {sum,sumsq}]
  __shared__ float c0s[2];
  __shared__ int   tok2[2];

  const int rank = blockIdx.x;
  const int b    = blockIdx.y;
  const int tid  = threadIdx.x;
  const int w    = tid >> 5, l = tid & 31;
  const int base = rank * 32;
  const int mat  = w >> 1, half = w & 1;     // matvec role
  const int head = w >> 2, gm = rank*4 + (w & 3);  // mover-dot role

  // ---- register-resident state ----
  ull aR[64];
  {
    const float* asrc = (mat==0) ? gA1 : (mat==1) ? Wv1 : (mat==2) ? gA2 : Wv2;
    const ull* s8 = (const ull*)(asrc + (base + l)*Dv + half*128);
    #pragma unroll
    for (int i = 0; i < 64; i++) aR[i] = s8[i];
  }
  float biasR = 0.f;
  if (half == 0){
    const float* bsrc = (mat==0) ? gu1 : (mat==1) ? bv1 : (mat==2) ? gu2 : bv2;
    biasR = bsrc[base + l];
  }
  float uR[8];
  {
    const float* Usrc = head ? gU2 : gU1;
    #pragma unroll
    for (int i = 0; i < 8; i++) uR[i] = Usrc[gm*Dv + l + 32*i];
  }
  const float cR = (head ? gc2 : gc1)[gm];
  ull VmP[32];
  #pragma unroll
  for (int m = 0; m < Mm; m++){
    unsigned a = __float_as_uint(gVmv1[m*Dv + tid]);
    unsigned bq = __float_as_uint(gVmv2[m*Dv + tid]);
    VmP[m] = (ull)a | ((ull)bq << 32);
  }
  const float gamR = gamma[tid], betR = beta[tid];
  if (tid < 2) c0s[tid] = gc0v[tid];
  if (tid == 0) tok2[1] = seq[b*Tt + 1];
  {
    int tok0 = seq[b*Tt];
    zc[tid] = hidden[b*2*Dv + tid] + emb[(size_t)tok0*Dv + tid] * 16.0f;
    hv[tid] = hidden[b*2*Dv + Dv + tid];
  }
  __syncthreads();
  cluster_sync();

  float hn = 0.f;

  for (int t = 0; t < Tt; t++){
    const int bsel = t & 1;
    // prefetch: token idx 2 ahead; emb row 1 ahead
    int tk = 0;
    if (tid == 0 && t + 2 < Tt) tk = __ldg(seq + b*Tt + t + 2);
    float xn = 0.f;
    if (t + 1 < Tt) xn = __ldg(emb + (size_t)tok2[(t + 1) & 1]*Dv + tid) * 16.0f;

    // ---- matvec from registers (packed f32x2) ----
    {
      const float* zin = (mat < 2) ? zc : hv;
      const ull* z8 = (const ull*)zin + half*64;
      ull a0 = 0, a1 = 0, a2 = 0, a3 = 0;
      #pragma unroll
      for (int i = 0; i < 16; i++){
        a0 = fma2(aR[4*i+0], z8[4*i+0], a0);
        a1 = fma2(aR[4*i+1], z8[4*i+1], a1);
        a2 = fma2(aR[4*i+2], z8[4*i+2], a2);
        a3 = fma2(aR[4*i+3], z8[4*i+3], a3);
      }
      ull s = add2(add2(a0, a1), add2(a2, a3));
      pr[w*32 + l] = lo32(s) + hi32(s) + biasR;
    }
    // ---- mover score dot + broadcast ----
    {
      const float* zz = head ? hv : zc;
      float md = 0.f;
      #pragma unroll
      for (int i = 0; i < 8; i++) md += uR[i]*zz[l + 32*i];
      md = wsum(md) + cR;
      if (l < 8)
        st_cluster_f32(mapa_rank(smem_u32(&sc[bsel][head*32 + gm]), l), md);
    }
    __syncthreads();   // bar1: pr complete

    // ---- combine halves; broadcast self partials (w0,w2) and v chunks (w1,w3) ----
    if (w < 4){
      float r = pr[(2*w)*32 + l] + pr[(2*w + 1)*32 + l];
      if ((w & 1) == 0){       // A-matvec: self-score partial
        const float* zz = (w == 0) ? zc : hv;
        float pp = wsum(zz[base + l] * r);
        if (l < 8)
          st_cluster_f32(mapa_rank(smem_u32(&selfp[bsel][rank*2 + (w >> 1)]), l), pp);
      } else {                 // V-matvec: broadcast value chunk to all peers
        unsigned la = smem_u32(&vb[bsel][w >> 1][base + l]);
        #pragma unroll
        for (int p = 0; p < 8; p++) st_cluster_f32(mapa_rank(la, p), r);
      }
    }
    cluster_sync();    // the ONLY cluster barrier per step

    // ---- softmax (warps 0,1; head = w), replicated per CTA ----
    if (w < 2){
      float s = sc[bsel][w*32 + l] * 0.0625f;
      float ps = c0s[w];
      #pragma unroll
      for (int r2 = 0; r2 < 8; r2++) ps += selfp[bsel][2*r2 + w];
      ps *= 0.0625f;
      float mx = fmaxf(wmax(s), ps);
      float e  = __expf(s - mx);
      float es = wsum(e);
      float eself = __expf(ps - mx);
      float inv = 1.0f / (es + eself);
      awI[2*l + w] = e * inv;
      if (l == 0) awS[w] = eself * inv;
    }
    __syncthreads();   // bar2: aw ready

    // ---- replicated y (j = tid), VmP from registers ----
    float y;
    {
      const ull* aw8 = (const ull*)awI;
      ull acc = 0, accb = 0;
      #pragma unroll
      for (int m = 0; m < Mm; m += 2){
        acc  = fma2(aw8[m],     VmP[m],     acc);
        accb = fma2(aw8[m + 1], VmP[m + 1], accb);
      }
      acc = add2(acc, accb);
      float dg = lo32(acc) + hi32(acc)
               + awS[0]*vb[bsel][0][tid] + awS[1]*vb[bsel][1][tid];
      y = zc[tid] + dg;
    }

    // ---- replicated LayerNorm ----
    {
      float s1 = wsum(y), s2 = wsum(y*y);
      if (l == 0){ lnp[w*2] = s1; lnp[w*2 + 1] = s2; }
    }
    __syncthreads();   // bar3: LN partials
    {
      float t1 = 0.f, t2 = 0.f;
      #pragma unroll
      for (int r2 = 0; r2 < 8; r2++){ t1 += lnp[2*r2]; t2 += lnp[2*r2 + 1]; }
      float mu  = t1 * (1.0f/Dv);
      float var = t2 * (1.0f/Dv) - mu*mu;
      float rs  = rsqrtf(var + EPSv);
      hn = (y - mu)*rs*gamR + betR;
      if (tid == 0 && t + 2 < Tt) tok2[t & 1] = tk;
      zc[tid] = hn + xn;
      hv[tid] = hn;
    }
    __syncthreads();   // bar4: state ready for next step
  }

  if (rank == 0){
    out[b*2*Dv + tid]      = hn;
    out[b*2*Dv + Dv + tid] = hn;
    gZfin[b*Dv + tid]      = hn;
  }
}

// ------------------------ vocab epilogue ------------------------
__global__ void __launch_bounds__(256) k_logits(const float* __restrict__ Wvoc,
                                                const float* __restrict__ bvoc,
                                                float* __restrict__ yout)
{
  __shared__ float zT[Dv*16];      // [d][b]
  __shared__ float Ws[16*260];
  int tid = threadIdx.x;
  for (int i = 0; i < 16; i++){
    int idx = tid + i*256;
    int bb = idx >> 8, d = idx & 255;
    zT[d*16 + bb] = gZfin[bb*Dv + d];
  }
  int v0 = blockIdx.x * 64;
  __syncthreads();
  for (int pass = 0; pass < 4; pass++){
    int vb = v0 + pass*16;
    for (int i = 0; i < 16; i++){
      int idx = tid + i*256;
      int r = idx >> 8, c = idx & 255;
      Ws[r*260 + c] = (vb + r < Vv) ? Wvoc[(size_t)(vb + r)*Dv + c] : 0.f;
    }
    __syncthreads();
    int bb = tid >> 4, vl = tid & 15;
    int v = vb + vl;
    float acc = (v < Vv) ? bvoc[v] : 0.f;
    #pragma unroll 8
    for (int d = 0; d < Dv; d++) acc += Ws[vl*260 + d]*zT[d*16 + bb];
    if (v < Vv) yout[(size_t)bb*Vv + v] = acc;
    __syncthreads();
  }
}

__global__ void __launch_bounds__(1024) k_lse(const float* __restrict__ yout){
  int b = blockIdx.x, tid = threadIdx.x;
  __shared__ float red[1024];
  float mx = -1e30f;
  for (int v = tid; v < Vv; v += 1024) mx = fmaxf(mx, yout[(size_t)b*Vv + v]);
  red[tid] = mx; __syncthreads();
  for (int s = 512; s; s >>= 1){ if (tid < s) red[tid] = fmaxf(red[tid], red[tid + s]); __syncthreads(); }
  mx = red[0]; __syncthreads();
  float sum = 0.f;
  for (int v = tid; v < Vv; v += 1024) sum += __expf(yout[(size_t)b*Vv + v] - mx);
  red[tid] = sum; __syncthreads();
  for (int s = 512; s; s >>= 1){ if (tid < s) red[tid] += red[tid + s]; __syncthreads(); }
  if (tid == 0) gLse[b] = mx + logf(red[0]);
}

__global__ void k_sub(float* __restrict__ yout){
  int i = blockIdx.x*256 + threadIdx.x;
  if (i < Bn*Vv) yout[i] -= gLse[i / Vv];
}

// ------------------------ launch ------------------------
extern "C" void kernel_launch(void* const* d_in, const int* in_sizes, int n_in,
                              void* d_out, int out_size)
{
  const float* hidden = (const float*)d_in[0];
  const int*   seq    = (const int*)  d_in[1];
  const float* emb    = (const float*)d_in[2];
  const float* Wq1 = (const float*)d_in[3];  const float* bq1 = (const float*)d_in[4];
  const float* Wk1 = (const float*)d_in[5];  const float* bk1 = (const float*)d_in[6];
  const float* Wv1 = (const float*)d_in[7];  const float* bv1 = (const float*)d_in[8];
  const float* Wq2 = (const float*)d_in[9];  const float* bq2 = (const float*)d_in[10];
  const float* Wk2 = (const float*)d_in[11]; const float* bk2 = (const float*)d_in[12];
  const float* Wv2 = (const float*)d_in[13]; const float* bv2 = (const float*)d_in[14];
  const float* mv1 = (const float*)d_in[15]; const float* mv2 = (const float*)d_in[16];
  const float* gamma = (const float*)d_in[17];
  const float* beta  = (const float*)d_in[18];
  const float* Wvoc  = (const float*)d_in[19];
  const float* bvoc  = (const float*)d_in[20];
  float* out = (float*)d_out;
  float* yout = out + Bn*2*Dv;

  pk_A <<<dim3(Dv, 2), 256>>>(Wq1, Wk1, Wq2, Wk2);
  pk_KV<<<dim3(Mm, 4), 256>>>(mv1, mv2, Wk1, bk1, Wk2, bk2, Wv1, bv1, Wv2, bv2);
  pk_u <<<2, 256>>>(bq1, Wk1, bk1, Wq1, bq2, Wk2, bk2, Wq2);
  pk_U <<<dim3(Mm, 2), 256>>>(Wq1, bq1, Wq2, bq2);

  rnn_kernel<<<dim3(8, Bn), 256>>>(hidden, seq, emb, Wv1, bv1, Wv2, bv2,
                                   gamma, beta, out);

  k_logits<<<(Vv + 63)/64, 256>>>(Wvoc, bvoc, yout);
  k_lse<<<Bn, 1024>>>(yout);
  k_sub<<<(Bn*Vv + 255)/256, 256>>>(yout);
}